// round 1
// baseline (speedup 1.0000x reference)
#include <cuda_runtime.h>
#include <cstdint>

// ---------------- problem constants ----------------
#define N_NODES 100000
#define N_EDGES 1600000
#define C_IN    500
#define C       40        // n_classes
#define H       64        // hidden
#define ALPHA   0.1f
#define K_HOPS  10

// ---------------- static scratch (no allocations allowed) ----------------
__device__ float g_h0[N_NODES * C];
__device__ float g_bufA[N_NODES * C];
__device__ float g_bufB[N_NODES * C];
__device__ int   g_deg_out[N_NODES];
__device__ int   g_deg_in[N_NODES];
__device__ float g_inv_out[N_NODES];
__device__ float g_inv_in[N_NODES];
__device__ int   g_off[N_NODES + 1];
__device__ int   g_cursor[N_NODES];
__device__ int   g_csr_src[N_EDGES];
__device__ float g_csr_norm[N_EDGES];

// ============================================================
// 1) scores = x @ W_base + b_base   [N, 40]
//    256 rows/block, 1 row/thread, W in SMEM (float4 reads),
//    x tiles staged in SMEM (padded to kill bank conflicts).
// ============================================================
#define GB_ROWS 256
#define GB_KT   64
#define GEMM_SMEM ((C_IN * C + GB_ROWS * (GB_KT + 1)) * 4)

__global__ __launch_bounds__(GB_ROWS) void gemm_base_kernel(
    const float* __restrict__ x, const float* __restrict__ Wb,
    const float* __restrict__ bb, float* __restrict__ scores)
{
    extern __shared__ float sh[];
    float* Ws = sh;                      // [500][40]
    float* xs = sh + C_IN * C;           // [256][65]
    __shared__ float bs[C];

    const int tid = threadIdx.x;
    for (int i = tid; i < C_IN * C; i += GB_ROWS) Ws[i] = Wb[i];
    if (tid < C) bs[tid] = bb[tid];

    const int row = blockIdx.x * GB_ROWS + tid;
    float acc[C];
#pragma unroll
    for (int c = 0; c < C; c++) acc[c] = 0.f;

    const int warp = tid >> 5, lane = tid & 31;

    for (int k0 = 0; k0 < C_IN; k0 += GB_KT) {
        const int kt = min(GB_KT, C_IN - k0);
        __syncthreads();
        // stage x tile (coalesced within rows)
        for (int r = warp; r < GB_ROWS; r += 8) {
            const int grow = blockIdx.x * GB_ROWS + r;
            if (grow < N_NODES) {
                const float* xr = x + (size_t)grow * C_IN + k0;
                for (int k = lane; k < kt; k += 32)
                    xs[r * (GB_KT + 1) + k] = xr[k];
            } else {
                for (int k = lane; k < kt; k += 32)
                    xs[r * (GB_KT + 1) + k] = 0.f;
            }
        }
        __syncthreads();

        const float4* Ws4 = (const float4*)Ws;   // [500][10]
#pragma unroll 4
        for (int k = 0; k < kt; k++) {
            const float xv = xs[tid * (GB_KT + 1) + k];
            const float4* wrow = Ws4 + (size_t)(k0 + k) * (C / 4);
#pragma unroll
            for (int c4 = 0; c4 < C / 4; c4++) {
                const float4 w = wrow[c4];
                acc[c4 * 4 + 0] += xv * w.x;
                acc[c4 * 4 + 1] += xv * w.y;
                acc[c4 * 4 + 2] += xv * w.z;
                acc[c4 * 4 + 3] += xv * w.w;
            }
        }
    }

    if (row < N_NODES) {
        float4* out4 = (float4*)(scores + (size_t)row * C);
#pragma unroll
        for (int c4 = 0; c4 < C / 4; c4++) {
            float4 v;
            v.x = acc[c4 * 4 + 0] + bs[c4 * 4 + 0];
            v.y = acc[c4 * 4 + 1] + bs[c4 * 4 + 1];
            v.z = acc[c4 * 4 + 2] + bs[c4 * 4 + 2];
            v.w = acc[c4 * 4 + 3] + bs[c4 * 4 + 3];
            out4[c4] = v;
        }
    }
}

// ============================================================
// 2) h0 = (relu(softmax(scores) @ W1 + b1)) @ W2 + b2
//    1 node/thread; probs staged in SMEM (lane-striped),
//    h1[64] fully in registers.
// ============================================================
#define MLP_BS 128
__global__ __launch_bounds__(MLP_BS) void mlp_kernel(
    const float* __restrict__ scores, float* __restrict__ h0,
    const float* __restrict__ W1, const float* __restrict__ b1,
    const float* __restrict__ W2, const float* __restrict__ b2)
{
    __shared__ float W1s[C * H];      // [40][64]
    __shared__ float W2s[H * C];      // [64][40]
    __shared__ float b1s[H];
    __shared__ float b2s[C];
    __shared__ float p_sh[C * MLP_BS];

    const int tid = threadIdx.x;
    for (int i = tid; i < C * H; i += MLP_BS) W1s[i] = W1[i];
    for (int i = tid; i < H * C; i += MLP_BS) W2s[i] = W2[i];
    if (tid < H) b1s[tid] = b1[tid];
    if (tid < C) b2s[tid] = b2[tid];
    __syncthreads();

    const int node = blockIdx.x * MLP_BS + tid;
    if (node >= N_NODES) return;

    // load scores row, track max
    const float4* sc4 = (const float4*)(scores + (size_t)node * C);
    float m = -1e30f;
#pragma unroll
    for (int q = 0; q < C / 4; q++) {
        const float4 v = sc4[q];
        p_sh[(q * 4 + 0) * MLP_BS + tid] = v.x;
        p_sh[(q * 4 + 1) * MLP_BS + tid] = v.y;
        p_sh[(q * 4 + 2) * MLP_BS + tid] = v.z;
        p_sh[(q * 4 + 3) * MLP_BS + tid] = v.w;
        m = fmaxf(m, fmaxf(fmaxf(v.x, v.y), fmaxf(v.z, v.w)));
    }
    // softmax
    float s = 0.f;
    for (int i = 0; i < C; i++) {
        const float e = __expf(p_sh[i * MLP_BS + tid] - m);
        p_sh[i * MLP_BS + tid] = e;
        s += e;
    }
    const float inv = 1.f / s;

    // h1 = relu(p @ W1 + b1)
    float h1[H];
#pragma unroll
    for (int j = 0; j < H; j++) h1[j] = b1s[j];
    for (int i = 0; i < C; i++) {
        const float pv = p_sh[i * MLP_BS + tid] * inv;
#pragma unroll
        for (int j = 0; j < H; j++) h1[j] += pv * W1s[i * H + j];
    }
#pragma unroll
    for (int j = 0; j < H; j++) h1[j] = fmaxf(h1[j], 0.f);

    // h0 = h1 @ W2 + b2
    float* hrow = h0 + (size_t)node * C;
    for (int c = 0; c < C; c++) {
        float a = b2s[c];
#pragma unroll
        for (int j = 0; j < H; j++) a += h1[j] * W2s[j * C + c];
        hrow[c] = a;
    }
}

// ============================================================
// 3) graph preprocessing: degrees, inv-sqrt, prefix scan, CSR fill
// ============================================================
__global__ void deg_kernel(const int* __restrict__ src, const int* __restrict__ dst)
{
    const int e = blockIdx.x * blockDim.x + threadIdx.x;
    if (e < N_EDGES) {
        atomicAdd(&g_deg_out[src[e]], 1);
        atomicAdd(&g_deg_in[dst[e]], 1);
    }
}

__global__ void invsqrt_kernel()
{
    const int i = blockIdx.x * blockDim.x + threadIdx.x;
    if (i < N_NODES) {
        const int dso = g_deg_out[i];
        const int dsi = g_deg_in[i];
        g_inv_out[i] = dso > 0 ? rsqrtf((float)dso) : 0.f;
        g_inv_in[i]  = dsi > 0 ? rsqrtf((float)dsi) : 0.f;
    }
}

// single-block exclusive scan of g_deg_in -> g_off (also writes g_off[N])
#define SCAN_T 1024
__global__ __launch_bounds__(SCAN_T) void scan_kernel()
{
    __shared__ int part[SCAN_T];
    const int t = threadIdx.x;
    const int CH = (N_NODES + SCAN_T - 1) / SCAN_T;
    const int base = t * CH;
    int s = 0;
    for (int i = 0; i < CH; i++) {
        const int idx = base + i;
        if (idx < N_NODES) s += g_deg_in[idx];
    }
    part[t] = s;
    __syncthreads();
    // Hillis-Steele inclusive scan
    for (int o = 1; o < SCAN_T; o <<= 1) {
        const int v = (t >= o) ? part[t - o] : 0;
        __syncthreads();
        part[t] += v;
        __syncthreads();
    }
    int excl = part[t] - s;
    for (int i = 0; i < CH; i++) {
        const int idx = base + i;
        if (idx < N_NODES) {
            g_off[idx] = excl;
            excl += g_deg_in[idx];
        }
    }
    if (t == SCAN_T - 1) g_off[N_NODES] = part[SCAN_T - 1];
}

__global__ void cursor_kernel()
{
    const int i = blockIdx.x * blockDim.x + threadIdx.x;
    if (i < N_NODES) g_cursor[i] = g_off[i];
}

__global__ void fill_csr_kernel(const int* __restrict__ src, const int* __restrict__ dst)
{
    const int e = blockIdx.x * blockDim.x + threadIdx.x;
    if (e < N_EDGES) {
        const int s = src[e];
        const int d = dst[e];
        const int pos = atomicAdd(&g_cursor[d], 1);
        g_csr_src[pos] = s;
        g_csr_norm[pos] = g_inv_out[s] * g_inv_in[d];
    }
}

// ============================================================
// 4) one APPNP hop (pure gather, no atomics):
//    one warp per dst node; lanes own channels (0..31, 32..39).
// ============================================================
#define HOP_BS 256
__global__ __launch_bounds__(HOP_BS) void hop_kernel(
    const float* __restrict__ hin, const float* __restrict__ h0,
    float* __restrict__ hout)
{
    const int warp = threadIdx.x >> 5;
    const int lane = threadIdx.x & 31;
    const int node = blockIdx.x * (HOP_BS / 32) + warp;
    if (node >= N_NODES) return;

    const int beg = g_off[node];
    const int end = g_off[node + 1];

    float acc0 = 0.f, acc1 = 0.f;
#pragma unroll 4
    for (int e = beg; e < end; e++) {
        const int s = g_csr_src[e];          // uniform across warp -> broadcast
        const float nrm = g_csr_norm[e];
        const float* hr = hin + (size_t)s * C;
        acc0 += nrm * hr[lane];
        if (lane < C - 32) acc1 += nrm * hr[32 + lane];
    }

    const size_t o = (size_t)node * C;
    hout[o + lane] = (1.f - ALPHA) * acc0 + ALPHA * h0[o + lane];
    if (lane < C - 32)
        hout[o + 32 + lane] = (1.f - ALPHA) * acc1 + ALPHA * h0[o + 32 + lane];
}

// ============================================================
// launch
// ============================================================
extern "C" void kernel_launch(void* const* d_in, const int* in_sizes, int n_in,
                              void* d_out, int out_size)
{
    const float* x  = (const float*)d_in[0];
    const int*   ei = (const int*)d_in[1];
    const float* Wb = (const float*)d_in[2];
    const float* bb = (const float*)d_in[3];
    const float* W1 = (const float*)d_in[4];
    const float* b1 = (const float*)d_in[5];
    const float* W2 = (const float*)d_in[6];
    const float* b2 = (const float*)d_in[7];

    float* out = (float*)d_out;
    float* adjust = out;                              // [N, 40]
    float* scores = out + (size_t)N_NODES * C;        // [N, 40]

    const int* src = ei;
    const int* dst = ei + N_EDGES;

    cudaFuncSetAttribute(gemm_base_kernel,
                         cudaFuncAttributeMaxDynamicSharedMemorySize, GEMM_SMEM);

    float *h0p, *Ap, *Bp;
    int *degop, *deginp;
    cudaGetSymbolAddress((void**)&h0p, g_h0);
    cudaGetSymbolAddress((void**)&Ap, g_bufA);
    cudaGetSymbolAddress((void**)&Bp, g_bufB);
    cudaGetSymbolAddress((void**)&degop, g_deg_out);
    cudaGetSymbolAddress((void**)&deginp, g_deg_in);

    cudaMemsetAsync(degop, 0, N_NODES * sizeof(int), 0);
    cudaMemsetAsync(deginp, 0, N_NODES * sizeof(int), 0);

    // base scorer + MLP
    gemm_base_kernel<<<(N_NODES + GB_ROWS - 1) / GB_ROWS, GB_ROWS, GEMM_SMEM>>>(
        x, Wb, bb, scores);
    mlp_kernel<<<(N_NODES + MLP_BS - 1) / MLP_BS, MLP_BS>>>(
        scores, h0p, W1, b1, W2, b2);

    // graph preprocessing
    deg_kernel<<<(N_EDGES + 255) / 256, 256>>>(src, dst);
    invsqrt_kernel<<<(N_NODES + 255) / 256, 256>>>();
    scan_kernel<<<1, SCAN_T>>>();
    cursor_kernel<<<(N_NODES + 255) / 256, 256>>>();
    fill_csr_kernel<<<(N_EDGES + 255) / 256, 256>>>(src, dst);

    // APPNP hops (ping-pong, final hop writes d_out directly)
    const int hop_grid = (N_NODES + (HOP_BS / 32) - 1) / (HOP_BS / 32);
    const float* hin = h0p;
    for (int k = 0; k < K_HOPS; k++) {
        float* o = (k == K_HOPS - 1) ? adjust : ((k % 2 == 0) ? Ap : Bp);
        hop_kernel<<<hop_grid, HOP_BS>>>(hin, h0p, o);
        hin = o;
    }
}